// round 13
// baseline (speedup 1.0000x reference)
#include <cuda_runtime.h>
#include <cuda_fp16.h>
#include <math.h>
#include <stdint.h>

// ---------------------------------------------------------------------------
// Actor_Soft_Attention: B=65536, IN=128, HID=256, OUT=8
// mma.sync m16n8k16 fp16/fp32; 512 threads (16 warps, 4Mx4N) for latency
// hiding; cp.async double-buffered weight stages; W4 as register B-frags;
// L4 fused from L3 C-fragments.
//
// pre-kernel: weights -> 18 pre-swizzled [128][128] fp16 stage blobs
// main (512 CTAs x 128 rows, 512 thr):
//   stages 0..7  : L1 per 64-ch chunk: W2 stage -> att, W1 stage -> h_i tiles
//   stages 8..17 : L3 x[128x256] over K=640 {h0,h1,s0,s1,s2} x 2 N-halves
//   at each N-half end: L4 oat += x-frag @ W4 (all-register)
//   final: cross-wn reduction in smem, tanh, store.
// ---------------------------------------------------------------------------

#define TILE   32768                   // 128 rows x 256B
#define NCTA   512

#define SM_A   0                       // 5 tiles: h0,h1,s0,s1,s2
#define SM_W   (5 * TILE)              // 163840: two 32KB stage buffers
#define SMEM_BYTES (7 * TILE)          // 229376

__device__ __align__(16) __half g_wstage[18 * 16384];  // 18 stage blobs

// swizzled byte offset inside a [128 rows][128 halves] tile (256B rows)
__host__ __device__ __forceinline__ uint32_t swz(int r, int ch) {
    return (uint32_t)(r * 256 + ((((ch >> 3) ^ (r & 7)) << 4)) + (ch & 7) * 2);
}

// ---------------- warp primitives ----------------
__device__ __forceinline__ uint32_t smem_u32(const void* p) {
    uint32_t a;
    asm("{ .reg .u64 t; cvta.to.shared.u64 t, %1; cvt.u32.u64 %0, t; }" : "=r"(a) : "l"(p));
    return a;
}
__device__ __forceinline__ void ldsm4(uint32_t* r, uint32_t a) {
    asm volatile("ldmatrix.sync.aligned.m8n8.x4.shared.b16 {%0,%1,%2,%3}, [%4];"
        : "=r"(r[0]), "=r"(r[1]), "=r"(r[2]), "=r"(r[3]) : "r"(a));
}
__device__ __forceinline__ void mma16816(float (&c)[4], const uint32_t a[4],
                                         uint32_t b0, uint32_t b1) {
    asm volatile("mma.sync.aligned.m16n8k16.row.col.f32.f16.f16.f32 "
        "{%0,%1,%2,%3}, {%4,%5,%6,%7}, {%8,%9}, {%0,%1,%2,%3};"
        : "+f"(c[0]), "+f"(c[1]), "+f"(c[2]), "+f"(c[3])
        : "r"(a[0]), "r"(a[1]), "r"(a[2]), "r"(a[3]), "r"(b0), "r"(b1));
}
__device__ __forceinline__ uint32_t packh2(float x, float y) {
    __half2 h = __floats2half2_rn(x, y);
    return *(uint32_t*)&h;
}
// 32KB stage prefetch (512 threads), one commit group
__device__ __forceinline__ void prefetch32k(uint32_t dst, const char* src, int t) {
    #pragma unroll
    for (int i = 0; i < 4; i++) {
        asm volatile("cp.async.cg.shared.global [%0], [%1], 16;"
            :: "r"(dst + (uint32_t)((t + 512 * i) * 16)), "l"(src + (t + 512 * i) * 16));
    }
    asm volatile("cp.async.commit_group;" ::: "memory");
}
#define CP_WAIT_ALL() asm volatile("cp.async.wait_group 0;" ::: "memory")

// C[32 x NT8*8] += A(32 rows,K=128) * W(NT8*8 n-rows,K=128)^T
template<int NT8>
__device__ __forceinline__ void wgemm1(float (&acc)[2][NT8][4],
    uint32_t aBase, int ax, int aHi, uint32_t bBase, int bx, int bHi)
{
    #pragma unroll
    for (int kb = 0; kb < 8; kb++) {
        uint32_t ka  = (uint32_t)(((((kb << 1) | aHi) ^ ax) << 4));
        uint32_t kbb = (uint32_t)(((((kb << 1) | bHi) ^ bx) << 4));
        uint32_t af[2][4], bf[NT8 / 2][4];
        ldsm4(af[0], aBase + ka);
        ldsm4(af[1], aBase + 4096 + ka);
        #pragma unroll
        for (int p = 0; p < NT8 / 2; p++) ldsm4(bf[p], bBase + p * 4096 + kbb);
        #pragma unroll
        for (int i = 0; i < 2; i++)
            #pragma unroll
            for (int j = 0; j < NT8; j++)
                mma16816(acc[i][j], af[i], bf[j >> 1][(j & 1) * 2], bf[j >> 1][(j & 1) * 2 + 1]);
    }
}
// two A tiles sharing one 16-n-row W tile (NT8=2)
__device__ __forceinline__ void wgemm2(float (&c1)[2][2][4], float (&c2)[2][2][4],
    uint32_t a1, uint32_t a2, int ax, int aHi, uint32_t bBase, int bx, int bHi)
{
    #pragma unroll
    for (int kb = 0; kb < 8; kb++) {
        uint32_t ka  = (uint32_t)(((((kb << 1) | aHi) ^ ax) << 4));
        uint32_t kbb = (uint32_t)(((((kb << 1) | bHi) ^ bx) << 4));
        uint32_t f1[2][4], f2[2][4], bf[4];
        ldsm4(f1[0], a1 + ka);  ldsm4(f1[1], a1 + 4096 + ka);
        ldsm4(f2[0], a2 + ka);  ldsm4(f2[1], a2 + 4096 + ka);
        ldsm4(bf, bBase + kbb);
        #pragma unroll
        for (int i = 0; i < 2; i++)
            #pragma unroll
            for (int j = 0; j < 2; j++) {
                mma16816(c1[i][j], f1[i], bf[j * 2], bf[j * 2 + 1]);
                mma16816(c2[i][j], f2[i], bf[j * 2], bf[j * 2 + 1]);
            }
    }
}

// ---------------- weight pre-conversion (18 stage blobs) ----------------
__global__ void convert_weights(const float* __restrict__ W1, const float* __restrict__ W2,
                                const float* __restrict__ W3)
{
    const int s = blockIdx.x, t = threadIdx.x;
    char* dst = (char*)(g_wstage + (size_t)s * 16384);
    for (int i = t; i < 4096; i += 256) {
        int r = i >> 5, kq = (i & 31) * 4;
        float4 v;
        if (s < 8) {
            int c0 = s >> 1;
            const float* src = (s & 1) ? W1 : W2;
            int wr = c0 * 64 + (r & 63);
            int wk = ((r >> 6) << 7) + kq;
            v = *(const float4*)(src + (size_t)wr * 256 + wk);
        } else {
            int u = s - 8, nh = u / 5, kc = u % 5;
            v = *(const float4*)(W3 + (size_t)(nh * 128 + r) * 640 + kc * 128 + kq);
        }
        char* d = dst + swz(r, kq);
        *(__half2*)d       = __floats2half2_rn(v.x, v.y);
        *(__half2*)(d + 4) = __floats2half2_rn(v.z, v.w);
    }
}

// ---------------- main kernel ----------------
__global__ __launch_bounds__(512, 1)
void actor_main(const float* __restrict__ state,
                const float* __restrict__ b1, const float* __restrict__ b2,
                const float* __restrict__ b3, const float* __restrict__ W4,
                const float* __restrict__ b4, float* __restrict__ out)
{
    extern __shared__ char smem[];
    const uint32_t sb = smem_u32(smem);
    const int t = threadIdx.x, wid = t >> 5, l = t & 31;
    const int wm = wid & 3, wn = wid >> 2;     // 4M x 4N
    const int g = l >> 2, tq = l & 3;
    const int cta = blockIdx.x;

    // ldmatrix lane geometry
    const int aRow = l & 15, aHi = l >> 4, ax = l & 7;
    const int bRow = (l & 7) + ((l >> 4) & 1) * 8, bHi = (l >> 3) & 1, bx = l & 7;

    // ---- W4 register B-fragments (n=8 outputs, k = nh*128 + wn*32 + kb*16) ----
    uint32_t w4f[2][2][2];
    {
        const int o = l >> 2, r2 = (l & 3) * 2;
        #pragma unroll
        for (int nh = 0; nh < 2; nh++)
            #pragma unroll
            for (int kb = 0; kb < 2; kb++) {
                int kbase = nh * 128 + wn * 32 + kb * 16;
                float2 v0 = *(const float2*)&W4[(size_t)o * 256 + kbase + r2];
                float2 v1 = *(const float2*)&W4[(size_t)o * 256 + kbase + r2 + 8];
                w4f[nh][kb][0] = packh2(v0.x, v0.y);
                w4f[nh][kb][1] = packh2(v1.x, v1.y);
            }
    }

    // ---- pipeline prologue: stage0 prefetch, then state staging ----
    prefetch32k(sb + SM_W, (const char*)g_wstage, t);

    {   // state -> swizzled fp16 tiles 2,3,4
        const float4* gs = (const float4*)(state + (size_t)cta * 128 * 384);
        for (int i4 = t; i4 < 12288; i4 += 512) {
            int r = i4 / 96, cq = (i4 % 96) * 4;
            float4 v = gs[i4];
            char* d = smem + SM_A + (2 + (cq >> 7)) * TILE + swz(r, cq & 127);
            *(__half2*)d       = __floats2half2_rn(v.x, v.y);
            *(__half2*)(d + 4) = __floats2half2_rn(v.z, v.w);
        }
    }

    // per-warp A fragment bases (32 rows per M-warp)
    const uint32_t aS0 = sb + SM_A + 2 * TILE + (uint32_t)((wm * 32 + aRow) * 256);
    const uint32_t aS1 = aS0 + TILE, aS2 = aS0 + 2 * TILE;

    // =====================================================================
    // L1 pipeline: stages 0..7 (per c0: W2 stage even, W1 stage odd)
    // warp covers 16 channels: wn*16 within the 64-ch chunk
    // =====================================================================
    float att[2][2][4];
    for (int s = 0; s < 8; s++) {
        CP_WAIT_ALL();
        __syncthreads();
        prefetch32k(sb + SM_W + (uint32_t)(((s + 1) & 1) * TILE),
                    (const char*)g_wstage + (size_t)(s + 1) * TILE, t);
        const uint32_t wb  = sb + SM_W + (uint32_t)((s & 1) * TILE);
        const uint32_t bWa = wb + (uint32_t)((wn * 16 + bRow) * 256);
        const uint32_t bWb = bWa + 64 * 256;
        const int c0 = s >> 1;

        float p0[2][2][4] = {}, p1[2][2][4] = {}, p2[2][2][4] = {};
        wgemm1<2>(p0, aS0, ax, aHi, bWa, bx, bHi);
        wgemm2(p1, p2, aS1, aS2, ax, aHi, bWb, bx, bHi);

        if (!(s & 1)) {
            // W2 stage -> attention coefficient
            #pragma unroll
            for (int j = 0; j < 2; j++) {
                int colg = c0 * 64 + wn * 16 + j * 8 + 2 * tq;
                float bb0 = __ldg(&b2[colg]), bb1 = __ldg(&b2[colg + 1]);
                #pragma unroll
                for (int i = 0; i < 2; i++)
                    #pragma unroll
                    for (int e = 0; e < 4; e++) {
                        float bb = (e & 1) ? bb1 : bb0;
                        float e0 = fmaxf(p0[i][j][e] + p1[i][j][e] + bb, 0.0f);
                        float e1 = fmaxf(p0[i][j][e] + p2[i][j][e] + bb, 0.0f);
                        att[i][j][e] = __fdividef(1.0f, 1.0f + __expf(e1 - e0));
                    }
            }
        } else {
            // W1 stage -> h_i into tiles 0/1
            #pragma unroll
            for (int j = 0; j < 2; j++) {
                int colg = c0 * 64 + wn * 16 + j * 8 + 2 * tq;
                float bb0 = __ldg(&b1[colg]), bb1 = __ldg(&b1[colg + 1]);
                #pragma unroll
                for (int i = 0; i < 2; i++)
                    #pragma unroll
                    for (int eh = 0; eh < 2; eh++) {
                        float hv[2];
                        #pragma unroll
                        for (int p = 0; p < 2; p++) {
                            int e = eh * 2 + p;
                            float bb = p ? bb1 : bb0;
                            float h0 = fmaxf(p0[i][j][e] + p1[i][j][e] + bb, 0.0f);
                            float h1 = fmaxf(p0[i][j][e] + p2[i][j][e] + bb, 0.0f);
                            hv[p] = fmaf(att[i][j][e], h0 - h1, h1);
                        }
                        int row = wm * 32 + i * 16 + g + eh * 8;
                        char* d = smem + SM_A + (colg >> 7) * TILE + swz(row, colg & 127);
                        *(__half2*)d = __floats2half2_rn(hv[0], hv[1]);
                    }
            }
        }
    }

    // =====================================================================
    // L3 + L4 pipeline: stages 8..17 (nh = (s-8)/5, kc = (s-8)%5)
    // warp covers 32 channels: wn*32 within the 128-ch N half
    // =====================================================================
    float oat[2][4] = {};
    float xacc[2][4][4];
    for (int s = 8; s < 18; s++) {
        CP_WAIT_ALL();
        __syncthreads();
        if (s < 17)
            prefetch32k(sb + SM_W + (uint32_t)(((s + 1) & 1) * TILE),
                        (const char*)g_wstage + (size_t)(s + 1) * TILE, t);
        const uint32_t wb = sb + SM_W + (uint32_t)((s & 1) * TILE);
        const int u = s - 8, nh = u / 5, kc = u % 5;

        if (kc == 0) {
            #pragma unroll
            for (int i = 0; i < 2; i++)
                #pragma unroll
                for (int j = 0; j < 4; j++)
                    #pragma unroll
                    for (int e = 0; e < 4; e++) xacc[i][j][e] = 0.0f;
        }

        wgemm1<4>(xacc,
                  sb + SM_A + kc * TILE + (uint32_t)((wm * 32 + aRow) * 256), ax, aHi,
                  wb + (uint32_t)((wn * 32 + bRow) * 256), bx, bHi);

        if (kc == 4) {
            // L4: relu+b3, pack C-frags as A-frags, mma with register W4 frags
            float b3v[4][2];
            #pragma unroll
            for (int j = 0; j < 4; j++) {
                int c = nh * 128 + wn * 32 + j * 8 + 2 * tq;
                b3v[j][0] = __ldg(&b3[c]);
                b3v[j][1] = __ldg(&b3[c + 1]);
            }
            #pragma unroll
            for (int i = 0; i < 2; i++)
                #pragma unroll
                for (int kb = 0; kb < 2; kb++) {
                    int j0 = kb * 2;
                    uint32_t af[4];
                    af[0] = packh2(fmaxf(xacc[i][j0][0]     + b3v[j0][0],     0.0f),
                                   fmaxf(xacc[i][j0][1]     + b3v[j0][1],     0.0f));
                    af[1] = packh2(fmaxf(xacc[i][j0][2]     + b3v[j0][0],     0.0f),
                                   fmaxf(xacc[i][j0][3]     + b3v[j0][1],     0.0f));
                    af[2] = packh2(fmaxf(xacc[i][j0 + 1][0] + b3v[j0 + 1][0], 0.0f),
                                   fmaxf(xacc[i][j0 + 1][1] + b3v[j0 + 1][1], 0.0f));
                    af[3] = packh2(fmaxf(xacc[i][j0 + 1][2] + b3v[j0 + 1][0], 0.0f),
                                   fmaxf(xacc[i][j0 + 1][3] + b3v[j0 + 1][1], 0.0f));
                    mma16816(oat[i], af, w4f[nh][kb][0], w4f[nh][kb][1]);
                }
        }
    }

    // =====================================================================
    // final: cross-wn reduction (4 partials), bias, tanh, store
    // =====================================================================
    __syncthreads();
    float* red = (float*)(smem + SM_W);   // 12KB, stage buffers free now
    if (wn > 0) {
        #pragma unroll
        for (int i = 0; i < 2; i++) {
            int r0 = wm * 32 + i * 16 + g;
            *(float2*)&red[((wn - 1) * 128 + r0) * 8 + 2 * tq] =
                make_float2(oat[i][0], oat[i][1]);
            *(float2*)&red[((wn - 1) * 128 + r0 + 8) * 8 + 2 * tq] =
                make_float2(oat[i][2], oat[i][3]);
        }
    }
    __syncthreads();
    if (wn == 0) {
        float bb0 = __ldg(&b4[2 * tq]), bb1 = __ldg(&b4[2 * tq + 1]);
        #pragma unroll
        for (int i = 0; i < 2; i++) {
            int r0 = wm * 32 + i * 16 + g;
            size_t gr = (size_t)cta * 128 + r0;
            float s00 = oat[i][0], s01 = oat[i][1], s10 = oat[i][2], s11 = oat[i][3];
            #pragma unroll
            for (int w = 0; w < 3; w++) {
                float2 v0 = *(float2*)&red[(w * 128 + r0) * 8 + 2 * tq];
                float2 v1 = *(float2*)&red[(w * 128 + r0 + 8) * 8 + 2 * tq];
                s00 += v0.x; s01 += v0.y; s10 += v1.x; s11 += v1.y;
            }
            *(float2*)&out[gr * 8 + 2 * tq] =
                make_float2(tanhf(s00 + bb0), tanhf(s01 + bb1));
            *(float2*)&out[(gr + 8) * 8 + 2 * tq] =
                make_float2(tanhf(s10 + bb0), tanhf(s11 + bb1));
        }
    }
}

// ---------------------------------------------------------------------------
// kernel_launch — 2 launches, graph-capturable, allocation-free.
// Inputs: state, W1, b1, W2, b2, W3, b3, W4, b4
// ---------------------------------------------------------------------------
extern "C" void kernel_launch(void* const* d_in, const int* in_sizes, int n_in,
                              void* d_out, int out_size)
{
    const float* state = (const float*)d_in[0];
    const float* W1    = (const float*)d_in[1];
    const float* b1    = (const float*)d_in[2];
    const float* W2    = (const float*)d_in[3];
    const float* b2    = (const float*)d_in[4];
    const float* W3    = (const float*)d_in[5];
    const float* b3    = (const float*)d_in[6];
    const float* W4    = (const float*)d_in[7];
    const float* b4    = (const float*)d_in[8];
    float* out = (float*)d_out;

    cudaFuncSetAttribute(actor_main,
                         cudaFuncAttributeMaxDynamicSharedMemorySize, SMEM_BYTES);

    convert_weights<<<18, 256>>>(W1, W2, W3);
    actor_main<<<NCTA, 512, SMEM_BYTES>>>(state, b1, b2, b3, W4, b4, out);
}

// round 14
// speedup vs baseline: 1.0697x; 1.0697x over previous
#include <cuda_runtime.h>
#include <cuda_fp16.h>
#include <math.h>
#include <stdint.h>

// ---------------------------------------------------------------------------
// Actor_Soft_Attention: B=65536, IN=128, HID=256, OUT=8
// mma.sync m16n8k16 fp16/fp32, 256 threads (8 warps).
//  L1 (stages 0..7): as R12 — 32KB double-buffered stages, 4Mx2N warps.
//  L3 (stages 8..12): 64KB single-buffered stages [256n x 128K], 2Mx4N warps,
//     64x64 warp tiles (halves ldsm traffic per MAC; tensor-bound).
//  L4: per-warp K-split (wn owns 64 ch), register W4 frags, 4-way reduce.
// ---------------------------------------------------------------------------

#define TILE   32768                   // 128 rows x 256B
#define NCTA   512

#define SM_A   0                       // 5 tiles: h0,h1,s0,s1,s2
#define SM_W   (5 * TILE)              // 163840: L1 2x32KB bufs / L3 one 64KB
#define SMEM_BYTES (SM_W + 65536)      // 229376

// L1 blobs: 8 x 16384 halves; L3 blobs: 5 x 32768 halves
__device__ __align__(16) __half g_wstage[8 * 16384 + 5 * 32768];

// swizzled byte offset: row-major 256B rows, XOR chunk by (r&7)
__host__ __device__ __forceinline__ uint32_t swz(int r, int ch) {
    return (uint32_t)(r * 256 + ((((ch >> 3) ^ (r & 7)) << 4)) + (ch & 7) * 2);
}

// ---------------- warp primitives ----------------
__device__ __forceinline__ uint32_t smem_u32(const void* p) {
    uint32_t a;
    asm("{ .reg .u64 t; cvta.to.shared.u64 t, %1; cvt.u32.u64 %0, t; }" : "=r"(a) : "l"(p));
    return a;
}
__device__ __forceinline__ void ldsm4(uint32_t* r, uint32_t a) {
    asm volatile("ldmatrix.sync.aligned.m8n8.x4.shared.b16 {%0,%1,%2,%3}, [%4];"
        : "=r"(r[0]), "=r"(r[1]), "=r"(r[2]), "=r"(r[3]) : "r"(a));
}
__device__ __forceinline__ void mma16816(float (&c)[4], const uint32_t a[4],
                                         uint32_t b0, uint32_t b1) {
    asm volatile("mma.sync.aligned.m16n8k16.row.col.f32.f16.f16.f32 "
        "{%0,%1,%2,%3}, {%4,%5,%6,%7}, {%8,%9}, {%0,%1,%2,%3};"
        : "+f"(c[0]), "+f"(c[1]), "+f"(c[2]), "+f"(c[3])
        : "r"(a[0]), "r"(a[1]), "r"(a[2]), "r"(a[3]), "r"(b0), "r"(b1));
}
__device__ __forceinline__ uint32_t packh2(float x, float y) {
    __half2 h = __floats2half2_rn(x, y);
    return *(uint32_t*)&h;
}
// stage prefetch (256 threads), one commit group
__device__ __forceinline__ void prefetch32k(uint32_t dst, const char* src, int t) {
    #pragma unroll
    for (int i = 0; i < 8; i++)
        asm volatile("cp.async.cg.shared.global [%0], [%1], 16;"
            :: "r"(dst + (uint32_t)((t + 256 * i) * 16)), "l"(src + (t + 256 * i) * 16));
    asm volatile("cp.async.commit_group;" ::: "memory");
}
__device__ __forceinline__ void prefetch64k(uint32_t dst, const char* src, int t) {
    #pragma unroll
    for (int i = 0; i < 16; i++)
        asm volatile("cp.async.cg.shared.global [%0], [%1], 16;"
            :: "r"(dst + (uint32_t)((t + 256 * i) * 16)), "l"(src + (t + 256 * i) * 16));
    asm volatile("cp.async.commit_group;" ::: "memory");
}
#define CP_WAIT_ALL() asm volatile("cp.async.wait_group 0;" ::: "memory")

// ---- L1 gemms (R12): C[32 x NT8*8] += A(32r,K128) * W(NT8*8 n,K128)^T ----
template<int NT8>
__device__ __forceinline__ void wgemm1(float (&acc)[2][NT8][4],
    uint32_t aBase, int ax, int aHi, uint32_t bBase, int bx, int bHi)
{
    #pragma unroll
    for (int kb = 0; kb < 8; kb++) {
        uint32_t ka  = (uint32_t)(((((kb << 1) | aHi) ^ ax) << 4));
        uint32_t kbb = (uint32_t)(((((kb << 1) | bHi) ^ bx) << 4));
        uint32_t af[2][4], bf[NT8 / 2][4];
        ldsm4(af[0], aBase + ka);
        ldsm4(af[1], aBase + 4096 + ka);
        #pragma unroll
        for (int p = 0; p < NT8 / 2; p++) ldsm4(bf[p], bBase + p * 4096 + kbb);
        #pragma unroll
        for (int i = 0; i < 2; i++)
            #pragma unroll
            for (int j = 0; j < NT8; j++)
                mma16816(acc[i][j], af[i], bf[j >> 1][(j & 1) * 2], bf[j >> 1][(j & 1) * 2 + 1]);
    }
}
__device__ __forceinline__ void wgemm2(float (&c1)[2][4][4], float (&c2)[2][4][4],
    uint32_t a1, uint32_t a2, int ax, int aHi, uint32_t bBase, int bx, int bHi)
{
    #pragma unroll
    for (int kb = 0; kb < 8; kb++) {
        uint32_t ka  = (uint32_t)(((((kb << 1) | aHi) ^ ax) << 4));
        uint32_t kbb = (uint32_t)(((((kb << 1) | bHi) ^ bx) << 4));
        uint32_t f1[2][4], f2[2][4], bf[2][4];
        ldsm4(f1[0], a1 + ka);         ldsm4(f1[1], a1 + 4096 + ka);
        ldsm4(f2[0], a2 + ka);         ldsm4(f2[1], a2 + 4096 + ka);
        ldsm4(bf[0], bBase + kbb);     ldsm4(bf[1], bBase + 4096 + kbb);
        #pragma unroll
        for (int i = 0; i < 2; i++)
            #pragma unroll
            for (int j = 0; j < 4; j++) {
                uint32_t b0 = bf[j >> 1][(j & 1) * 2], b1 = bf[j >> 1][(j & 1) * 2 + 1];
                mma16816(c1[i][j], f1[i], b0, b1);
                mma16816(c2[i][j], f2[i], b0, b1);
            }
    }
}
// ---- L3 gemm: C[64 x 64] += A(64r,K128) * W(64n,K128)^T ----
__device__ __forceinline__ void wgemm_l3(float (&acc)[4][8][4],
    uint32_t aBase, int ax, int aHi, uint32_t bBase, int bx, int bHi)
{
    #pragma unroll
    for (int kb = 0; kb < 8; kb++) {
        uint32_t ka  = (uint32_t)(((((kb << 1) | aHi) ^ ax) << 4));
        uint32_t kbb = (uint32_t)(((((kb << 1) | bHi) ^ bx) << 4));
        uint32_t af[4][4], bf[4][4];
        #pragma unroll
        for (int i = 0; i < 4; i++) ldsm4(af[i], aBase + i * 4096 + ka);
        #pragma unroll
        for (int p = 0; p < 4; p++) ldsm4(bf[p], bBase + p * 4096 + kbb);
        #pragma unroll
        for (int i = 0; i < 4; i++)
            #pragma unroll
            for (int j = 0; j < 8; j++)
                mma16816(acc[i][j], af[i], bf[j >> 1][(j & 1) * 2], bf[j >> 1][(j & 1) * 2 + 1]);
    }
}

// ---------------- weight pre-conversion (8 L1 + 5 L3 blobs) ----------------
__global__ void convert_weights(const float* __restrict__ W1, const float* __restrict__ W2,
                                const float* __restrict__ W3)
{
    const int s = blockIdx.x, t = threadIdx.x;
    if (s < 8) {
        char* dst = (char*)(g_wstage + (size_t)s * 16384);
        for (int i = t; i < 4096; i += 256) {
            int r = i >> 5, kq = (i & 31) * 4;
            int c0 = s >> 1;
            const float* src = (s & 1) ? W1 : W2;
            int wr = c0 * 64 + (r & 63);
            int wk = ((r >> 6) << 7) + kq;
            float4 v = *(const float4*)(src + (size_t)wr * 256 + wk);
            char* d = dst + swz(r, kq);
            *(__half2*)d       = __floats2half2_rn(v.x, v.y);
            *(__half2*)(d + 4) = __floats2half2_rn(v.z, v.w);
        }
    } else {
        int kc = s - 8;
        char* dst = (char*)(g_wstage + 8 * 16384 + (size_t)kc * 32768);
        for (int i = t; i < 8192; i += 256) {
            int r = i >> 5, kq = (i & 31) * 4;
            float4 v = *(const float4*)(W3 + (size_t)r * 640 + kc * 128 + kq);
            char* d = dst + swz(r, kq);
            *(__half2*)d       = __floats2half2_rn(v.x, v.y);
            *(__half2*)(d + 4) = __floats2half2_rn(v.z, v.w);
        }
    }
}

// ---------------- main kernel ----------------
__global__ __launch_bounds__(256, 1)
void actor_main(const float* __restrict__ state,
                const float* __restrict__ b1, const float* __restrict__ b2,
                const float* __restrict__ b3, const float* __restrict__ W4,
                const float* __restrict__ b4, float* __restrict__ out)
{
    extern __shared__ char smem[];
    const uint32_t sb = smem_u32(smem);
    const int t = threadIdx.x, wid = t >> 5, l = t & 31;
    const int wm = wid & 3, wn = wid >> 2;     // L1: 4M x 2N
    const int wm2 = wid & 1, wn4 = wid >> 1;   // L3: 2M x 4N
    const int g = l >> 2, tq = l & 3;
    const int cta = blockIdx.x;

    const int aRow = l & 15, aHi = l >> 4, ax = l & 7;
    const int bRow = (l & 7) + ((l >> 4) & 1) * 8, bHi = (l >> 3) & 1, bx = l & 7;

    // ---- prologue: stage0 prefetch, state staging ----
    prefetch32k(sb + SM_W, (const char*)g_wstage, t);
    {
        const float4* gs = (const float4*)(state + (size_t)cta * 128 * 384);
        for (int i4 = t; i4 < 12288; i4 += 256) {
            int r = i4 / 96, cq = (i4 % 96) * 4;
            float4 v = gs[i4];
            char* d = smem + SM_A + (2 + (cq >> 7)) * TILE + swz(r, cq & 127);
            *(__half2*)d       = __floats2half2_rn(v.x, v.y);
            *(__half2*)(d + 4) = __floats2half2_rn(v.z, v.w);
        }
    }

    const uint32_t aS0 = sb + SM_A + 2 * TILE + (uint32_t)((wm * 32 + aRow) * 256);
    const uint32_t aS1 = aS0 + TILE, aS2 = aS0 + 2 * TILE;

    // =====================================================================
    // L1: stages 0..7 (per c0: W2 stage even -> att, W1 stage odd -> h_i)
    // =====================================================================
    float att[2][4][4];
    for (int s = 0; s < 8; s++) {
        CP_WAIT_ALL();
        __syncthreads();
        if (s < 7)
            prefetch32k(sb + SM_W + (uint32_t)(((s + 1) & 1) * TILE),
                        (const char*)g_wstage + (size_t)(s + 1) * TILE, t);
        const uint32_t wb  = sb + SM_W + (uint32_t)((s & 1) * TILE);
        const uint32_t bWa = wb + (uint32_t)((wn * 32 + bRow) * 256);
        const uint32_t bWb = bWa + 64 * 256;
        const int c0 = s >> 1;

        float p0[2][4][4] = {}, p1[2][4][4] = {}, p2[2][4][4] = {};
        wgemm1<4>(p0, aS0, ax, aHi, bWa, bx, bHi);
        wgemm2(p1, p2, aS1, aS2, ax, aHi, bWb, bx, bHi);

        if (!(s & 1)) {
            #pragma unroll
            for (int j = 0; j < 4; j++) {
                int colg = c0 * 64 + wn * 32 + j * 8 + 2 * tq;
                float bb0 = __ldg(&b2[colg]), bb1 = __ldg(&b2[colg + 1]);
                #pragma unroll
                for (int i = 0; i < 2; i++)
                    #pragma unroll
                    for (int e = 0; e < 4; e++) {
                        float bb = (e & 1) ? bb1 : bb0;
                        float e0 = fmaxf(p0[i][j][e] + p1[i][j][e] + bb, 0.0f);
                        float e1 = fmaxf(p0[i][j][e] + p2[i][j][e] + bb, 0.0f);
                        att[i][j][e] = __fdividef(1.0f, 1.0f + __expf(e1 - e0));
                    }
            }
        } else {
            #pragma unroll
            for (int j = 0; j < 4; j++) {
                int colg = c0 * 64 + wn * 32 + j * 8 + 2 * tq;
                float bb0 = __ldg(&b1[colg]), bb1 = __ldg(&b1[colg + 1]);
                #pragma unroll
                for (int i = 0; i < 2; i++)
                    #pragma unroll
                    for (int eh = 0; eh < 2; eh++) {
                        float hv[2];
                        #pragma unroll
                        for (int p = 0; p < 2; p++) {
                            int e = eh * 2 + p;
                            float bb = p ? bb1 : bb0;
                            float h0 = fmaxf(p0[i][j][e] + p1[i][j][e] + bb, 0.0f);
                            float h1 = fmaxf(p0[i][j][e] + p2[i][j][e] + bb, 0.0f);
                            hv[p] = fmaf(att[i][j][e], h0 - h1, h1);
                        }
                        int row = wm * 32 + i * 16 + g + eh * 8;
                        char* d = smem + SM_A + (colg >> 7) * TILE + swz(row, colg & 127);
                        *(__half2*)d = __floats2half2_rn(hv[0], hv[1]);
                    }
            }
        }
    }

    // =====================================================================
    // L3: 5 single-buffered 64KB stages; warp tile 64 rows x 64 ch
    // =====================================================================
    float xacc[4][8][4];
    #pragma unroll
    for (int i = 0; i < 4; i++)
        #pragma unroll
        for (int j = 0; j < 8; j++)
            #pragma unroll
            for (int e = 0; e < 4; e++) xacc[i][j][e] = 0.0f;

    const uint32_t aL3base = sb + SM_A + (uint32_t)((wm2 * 64 + aRow) * 256);
    const uint32_t bL3     = sb + SM_W + (uint32_t)((wn4 * 64 + bRow) * 256);

    for (int kc = 0; kc < 5; kc++) {
        __syncthreads();   // all warps done reading W buffer (or h_i written, kc=0)
        prefetch64k(sb + SM_W, (const char*)g_wstage + 8 * 32768 + (size_t)kc * 65536, t);
        CP_WAIT_ALL();
        __syncthreads();
        wgemm_l3(xacc, aL3base + (uint32_t)(kc * TILE), ax, aHi, bL3, bx, bHi);
    }

    // =====================================================================
    // L4: relu+b3, pack C-frags as A-frags, mma vs register W4 (k-split by wn4)
    // =====================================================================
    float oat[4][4] = {};
    {
        uint32_t w4f[4][2];
        const int o = l >> 2, r2 = (l & 3) * 2;
        #pragma unroll
        for (int kb4 = 0; kb4 < 4; kb4++) {
            int kbase = wn4 * 64 + kb4 * 16;
            float2 v0 = *(const float2*)&W4[(size_t)o * 256 + kbase + r2];
            float2 v1 = *(const float2*)&W4[(size_t)o * 256 + kbase + r2 + 8];
            w4f[kb4][0] = packh2(v0.x, v0.y);
            w4f[kb4][1] = packh2(v1.x, v1.y);
        }
        float b3v[8][2];
        #pragma unroll
        for (int j = 0; j < 8; j++) {
            int c = wn4 * 64 + j * 8 + 2 * tq;
            b3v[j][0] = __ldg(&b3[c]);
            b3v[j][1] = __ldg(&b3[c + 1]);
        }
        #pragma unroll
        for (int i = 0; i < 4; i++)
            #pragma unroll
            for (int kb4 = 0; kb4 < 4; kb4++) {
                int j0 = kb4 * 2;
                uint32_t af[4];
                af[0] = packh2(fmaxf(xacc[i][j0][0]     + b3v[j0][0],     0.0f),
                               fmaxf(xacc[i][j0][1]     + b3v[j0][1],     0.0f));
                af[1] = packh2(fmaxf(xacc[i][j0][2]     + b3v[j0][0],     0.0f),
                               fmaxf(xacc[i][j0][3]     + b3v[j0][1],     0.0f));
                af[2] = packh2(fmaxf(xacc[i][j0 + 1][0] + b3v[j0 + 1][0], 0.0f),
                               fmaxf(xacc[i][j0 + 1][1] + b3v[j0 + 1][1], 0.0f));
                af[3] = packh2(fmaxf(xacc[i][j0 + 1][2] + b3v[j0 + 1][0], 0.0f),
                               fmaxf(xacc[i][j0 + 1][3] + b3v[j0 + 1][1], 0.0f));
                mma16816(oat[i], af, w4f[kb4][0], w4f[kb4][1]);
            }
    }

    // ---- final: 4-way cross-wn4 reduction, bias, tanh, store ----
    __syncthreads();
    float* red = (float*)(smem + SM_W);   // 12KB, W buffer free now
    if (wn4 > 0) {
        #pragma unroll
        for (int i = 0; i < 4; i++) {
            int r0 = wm2 * 64 + i * 16 + g;
            *(float2*)&red[((wn4 - 1) * 128 + r0) * 8 + 2 * tq] =
                make_float2(oat[i][0], oat[i][1]);
            *(float2*)&red[((wn4 - 1) * 128 + r0 + 8) * 8 + 2 * tq] =
                make_float2(oat[i][2], oat[i][3]);
        }
    }
    __syncthreads();
    if (wn4 == 0) {
        float bb0 = __ldg(&b4[2 * tq]), bb1 = __ldg(&b4[2 * tq + 1]);
        #pragma unroll
        for (int i = 0; i < 4; i++) {
            int r0 = wm2 * 64 + i * 16 + g;
            size_t gr = (size_t)cta * 128 + r0;
            float s00 = oat[i][0], s01 = oat[i][1], s10 = oat[i][2], s11 = oat[i][3];
            #pragma unroll
            for (int w = 0; w < 3; w++) {
                float2 v0 = *(float2*)&red[(w * 128 + r0) * 8 + 2 * tq];
                float2 v1 = *(float2*)&red[(w * 128 + r0 + 8) * 8 + 2 * tq];
                s00 += v0.x; s01 += v0.y; s10 += v1.x; s11 += v1.y;
            }
            *(float2*)&out[gr * 8 + 2 * tq] =
                make_float2(tanhf(s00 + bb0), tanhf(s01 + bb1));
            *(float2*)&out[(gr + 8) * 8 + 2 * tq] =
                make_float2(tanhf(s10 + bb0), tanhf(s11 + bb1));
        }
    }
}

// ---------------------------------------------------------------------------
// kernel_launch — 2 launches, graph-capturable, allocation-free.
// Inputs: state, W1, b1, W2, b2, W3, b3, W4, b4
// ---------------------------------------------------------------------------
extern "C" void kernel_launch(void* const* d_in, const int* in_sizes, int n_in,
                              void* d_out, int out_size)
{
    const float* state = (const float*)d_in[0];
    const float* W1    = (const float*)d_in[1];
    const float* b1    = (const float*)d_in[2];
    const float* W2    = (const float*)d_in[3];
    const float* b2    = (const float*)d_in[4];
    const float* W3    = (const float*)d_in[5];
    const float* b3    = (const float*)d_in[6];
    const float* W4    = (const float*)d_in[7];
    const float* b4    = (const float*)d_in[8];
    float* out = (float*)d_out;

    cudaFuncSetAttribute(actor_main,
                         cudaFuncAttributeMaxDynamicSharedMemorySize, SMEM_BYTES);

    convert_weights<<<13, 256>>>(W1, W2, W3);
    actor_main<<<NCTA, 256, SMEM_BYTES>>>(state, b1, b2, b3, W4, b4, out);
}

// round 16
// speedup vs baseline: 1.2000x; 1.1218x over previous
#include <cuda_runtime.h>
#include <cuda_fp16.h>
#include <math.h>
#include <stdint.h>

// ---------------------------------------------------------------------------
// Actor_Soft_Attention: B=65536, IN=128, HID=256, OUT=8
// mma.sync m16n8k16 fp16/fp32. BM=64 rows/CTA, 112KB smem -> 2 CTAs/SM:
// two independent barrier domains per SM hide each other's syncs/fetches.
//  L1 (stages 0..7): 32KB single-buffered stages, warps 4Mx2N (16r x 32ch).
//  L3 (stages 8..17): [128n x 128K] stages, warps 2Mx4N (32r x 32ch).
//  L4 fused from L3 C-fragments with register W4 B-frags; 4-way reduce.
// R16 fix: weight blob byte stride is WBLOB (32768 B), NOT TILE (16384 B) —
// R15 read stages at half-shifted offsets through a char* cast.
// ---------------------------------------------------------------------------

#define TILE   16384                   // 64 rows x 256B  (A-tile bytes)
#define WBLOB  32768                   // weight stage blob bytes (16384 halves)
#define NCTA   1024

#define SM_A   0                       // 5 tiles: h0,h1,s0,s1,s2 (80KB)
#define SM_W   (5 * TILE)              // 81920: one 32KB stage buffer
#define SMEM_BYTES (SM_W + 32768)      // 114688 -> 2 CTAs/SM

// 18 stage blobs: 8 L1 ([64ch x K0:128 | 64ch x K128:256]) + 10 L3 ([128n x 128K])
__device__ __align__(16) __half g_wstage[18 * 16384];

// swizzled byte offset: row-major 256B rows, XOR chunk by (r&7)
__host__ __device__ __forceinline__ uint32_t swz(int r, int ch) {
    return (uint32_t)(r * 256 + ((((ch >> 3) ^ (r & 7)) << 4)) + (ch & 7) * 2);
}

// ---------------- warp primitives ----------------
__device__ __forceinline__ uint32_t smem_u32(const void* p) {
    uint32_t a;
    asm("{ .reg .u64 t; cvta.to.shared.u64 t, %1; cvt.u32.u64 %0, t; }" : "=r"(a) : "l"(p));
    return a;
}
__device__ __forceinline__ void ldsm4(uint32_t* r, uint32_t a) {
    asm volatile("ldmatrix.sync.aligned.m8n8.x4.shared.b16 {%0,%1,%2,%3}, [%4];"
        : "=r"(r[0]), "=r"(r[1]), "=r"(r[2]), "=r"(r[3]) : "r"(a));
}
__device__ __forceinline__ void mma16816(float (&c)[4], const uint32_t a[4],
                                         uint32_t b0, uint32_t b1) {
    asm volatile("mma.sync.aligned.m16n8k16.row.col.f32.f16.f16.f32 "
        "{%0,%1,%2,%3}, {%4,%5,%6,%7}, {%8,%9}, {%0,%1,%2,%3};"
        : "+f"(c[0]), "+f"(c[1]), "+f"(c[2]), "+f"(c[3])
        : "r"(a[0]), "r"(a[1]), "r"(a[2]), "r"(a[3]), "r"(b0), "r"(b1));
}
__device__ __forceinline__ uint32_t packh2(float x, float y) {
    __half2 h = __floats2half2_rn(x, y);
    return *(uint32_t*)&h;
}
// 32KB stage prefetch (256 threads), one commit group
__device__ __forceinline__ void prefetch32k(uint32_t dst, const char* src, int t) {
    #pragma unroll
    for (int i = 0; i < 8; i++)
        asm volatile("cp.async.cg.shared.global [%0], [%1], 16;"
            :: "r"(dst + (uint32_t)((t + 256 * i) * 16)), "l"(src + (t + 256 * i) * 16));
    asm volatile("cp.async.commit_group;" ::: "memory");
}
#define CP_WAIT_ALL() asm volatile("cp.async.wait_group 0;" ::: "memory")

// ---- L1: C[16 x 32] += A(16r,K128) * W(32n,K128)^T ----
__device__ __forceinline__ void wgemmL1_one(float (&acc)[4][4],
    uint32_t aBase, int ax, int aHi, uint32_t bBase, int bx, int bHi)
{
    #pragma unroll
    for (int kb = 0; kb < 8; kb++) {
        uint32_t ka  = (uint32_t)(((((kb << 1) | aHi) ^ ax) << 4));
        uint32_t kbb = (uint32_t)(((((kb << 1) | bHi) ^ bx) << 4));
        uint32_t af[4], bf[2][4];
        ldsm4(af, aBase + ka);
        ldsm4(bf[0], bBase + kbb);
        ldsm4(bf[1], bBase + 4096 + kbb);
        #pragma unroll
        for (int j = 0; j < 4; j++)
            mma16816(acc[j], af, bf[j >> 1][(j & 1) * 2], bf[j >> 1][(j & 1) * 2 + 1]);
    }
}
// two A tiles sharing one 32-n-row W tile
__device__ __forceinline__ void wgemmL1_two(float (&c1)[4][4], float (&c2)[4][4],
    uint32_t a1, uint32_t a2, int ax, int aHi, uint32_t bBase, int bx, int bHi)
{
    #pragma unroll
    for (int kb = 0; kb < 8; kb++) {
        uint32_t ka  = (uint32_t)(((((kb << 1) | aHi) ^ ax) << 4));
        uint32_t kbb = (uint32_t)(((((kb << 1) | bHi) ^ bx) << 4));
        uint32_t f1[4], f2[4], bf[2][4];
        ldsm4(f1, a1 + ka);
        ldsm4(f2, a2 + ka);
        ldsm4(bf[0], bBase + kbb);
        ldsm4(bf[1], bBase + 4096 + kbb);
        #pragma unroll
        for (int j = 0; j < 4; j++) {
            uint32_t b0 = bf[j >> 1][(j & 1) * 2], b1 = bf[j >> 1][(j & 1) * 2 + 1];
            mma16816(c1[j], f1, b0, b1);
            mma16816(c2[j], f2, b0, b1);
        }
    }
}
// ---- L3: C[32 x 32] += A(32r,K128) * W(32n,K128)^T ----
__device__ __forceinline__ void wgemm_l3(float (&acc)[2][4][4],
    uint32_t aBase, int ax, int aHi, uint32_t bBase, int bx, int bHi)
{
    #pragma unroll
    for (int kb = 0; kb < 8; kb++) {
        uint32_t ka  = (uint32_t)(((((kb << 1) | aHi) ^ ax) << 4));
        uint32_t kbb = (uint32_t)(((((kb << 1) | bHi) ^ bx) << 4));
        uint32_t af[2][4], bf[2][4];
        ldsm4(af[0], aBase + ka);
        ldsm4(af[1], aBase + 4096 + ka);
        ldsm4(bf[0], bBase + kbb);
        ldsm4(bf[1], bBase + 4096 + kbb);
        #pragma unroll
        for (int i = 0; i < 2; i++)
            #pragma unroll
            for (int j = 0; j < 4; j++)
                mma16816(acc[i][j], af[i], bf[j >> 1][(j & 1) * 2], bf[j >> 1][(j & 1) * 2 + 1]);
    }
}

// ---------------- weight pre-conversion (18 blobs) ----------------
__global__ void convert_weights(const float* __restrict__ W1, const float* __restrict__ W2,
                                const float* __restrict__ W3)
{
    const int s = blockIdx.x, t = threadIdx.x;
    char* dst = (char*)g_wstage + (size_t)s * WBLOB;
    for (int i = t; i < 4096; i += 256) {
        int r = i >> 5, kq = (i & 31) * 4;
        float4 v;
        if (s < 8) {
            int c0 = s >> 1;
            const float* src = (s & 1) ? W1 : W2;
            int wr = c0 * 64 + (r & 63);
            int wk = ((r >> 6) << 7) + kq;
            v = *(const float4*)(src + (size_t)wr * 256 + wk);
        } else {
            int u = s - 8, nh = u / 5, kc = u % 5;
            v = *(const float4*)(W3 + (size_t)(nh * 128 + r) * 640 + kc * 128 + kq);
        }
        char* d = dst + swz(r, kq);
        *(__half2*)d       = __floats2half2_rn(v.x, v.y);
        *(__half2*)(d + 4) = __floats2half2_rn(v.z, v.w);
    }
}

// ---------------- main kernel ----------------
__global__ __launch_bounds__(256, 2)
void actor_main(const float* __restrict__ state,
                const float* __restrict__ b1, const float* __restrict__ b2,
                const float* __restrict__ b3, const float* __restrict__ W4,
                const float* __restrict__ b4, float* __restrict__ out)
{
    extern __shared__ char smem[];
    const uint32_t sb = smem_u32(smem);
    const int t = threadIdx.x, wid = t >> 5, l = t & 31;
    const int wm = wid & 3, wn = wid >> 2;     // L1: 4M x 2N (16r x 32ch)
    const int wm2 = wid & 1, wn4 = wid >> 1;   // L3: 2M x 4N (32r x 32ch)
    const int g = l >> 2, tq = l & 3;
    const int cta = blockIdx.x;

    const int aRow = l & 15, aHi = l >> 4, ax = l & 7;
    const int bRow = (l & 7) + ((l >> 4) & 1) * 8, bHi = (l >> 3) & 1, bx = l & 7;

    // ---- W4 register B-fragments: k = nh*128 + wn4*32 + kb*16 ----
    uint32_t w4f[2][2][2];
    {
        const int o = l >> 2, r2 = (l & 3) * 2;
        #pragma unroll
        for (int nh = 0; nh < 2; nh++)
            #pragma unroll
            for (int kb = 0; kb < 2; kb++) {
                int kbase = nh * 128 + wn4 * 32 + kb * 16;
                float2 v0 = *(const float2*)&W4[(size_t)o * 256 + kbase + r2];
                float2 v1 = *(const float2*)&W4[(size_t)o * 256 + kbase + r2 + 8];
                w4f[nh][kb][0] = packh2(v0.x, v0.y);
                w4f[nh][kb][1] = packh2(v1.x, v1.y);
            }
    }

    // ---- prologue: stage0 prefetch, then state staging ----
    prefetch32k(sb + SM_W, (const char*)g_wstage, t);
    {
        const float4* gs = (const float4*)(state + (size_t)cta * 64 * 384);
        for (int i4 = t; i4 < 6144; i4 += 256) {
            int r = i4 / 96, cq = (i4 % 96) * 4;
            float4 v = gs[i4];
            char* d = smem + SM_A + (2 + (cq >> 7)) * TILE + swz(r, cq & 127);
            *(__half2*)d       = __floats2half2_rn(v.x, v.y);
            *(__half2*)(d + 4) = __floats2half2_rn(v.z, v.w);
        }
    }

    const uint32_t aS0 = sb + SM_A + 2 * TILE + (uint32_t)((wm * 16 + aRow) * 256);
    const uint32_t aS1 = aS0 + TILE, aS2 = aS0 + 2 * TILE;

    // =====================================================================
    // L1: stages 0..7 (per c0: W2 stage even -> att, W1 stage odd -> h_i)
    // =====================================================================
    float att[4][4];
    for (int s = 0; s < 8; s++) {
        if (s) {
            __syncthreads();   // prior stage reads done
            prefetch32k(sb + SM_W, (const char*)g_wstage + (size_t)s * WBLOB, t);
        }
        CP_WAIT_ALL();
        __syncthreads();
        const uint32_t bWa = sb + SM_W + (uint32_t)((wn * 32 + bRow) * 256);
        const uint32_t bWb = bWa + 64 * 256;
        const int c0 = s >> 1;

        float p0[4][4] = {}, p1[4][4] = {}, p2[4][4] = {};
        wgemmL1_one(p0, aS0, ax, aHi, bWa, bx, bHi);
        wgemmL1_two(p1, p2, aS1, aS2, ax, aHi, bWb, bx, bHi);

        if (!(s & 1)) {
            #pragma unroll
            for (int j = 0; j < 4; j++) {
                int colg = c0 * 64 + wn * 32 + j * 8 + 2 * tq;
                float bb0 = __ldg(&b2[colg]), bb1 = __ldg(&b2[colg + 1]);
                #pragma unroll
                for (int e = 0; e < 4; e++) {
                    float bb = (e & 1) ? bb1 : bb0;
                    float e0 = fmaxf(p0[j][e] + p1[j][e] + bb, 0.0f);
                    float e1 = fmaxf(p0[j][e] + p2[j][e] + bb, 0.0f);
                    att[j][e] = __fdividef(1.0f, 1.0f + __expf(e1 - e0));
                }
            }
        } else {
            #pragma unroll
            for (int j = 0; j < 4; j++) {
                int colg = c0 * 64 + wn * 32 + j * 8 + 2 * tq;
                float bb0 = __ldg(&b1[colg]), bb1 = __ldg(&b1[colg + 1]);
                #pragma unroll
                for (int eh = 0; eh < 2; eh++) {
                    float hv[2];
                    #pragma unroll
                    for (int p = 0; p < 2; p++) {
                        int e = eh * 2 + p;
                        float bb = p ? bb1 : bb0;
                        float h0 = fmaxf(p0[j][e] + p1[j][e] + bb, 0.0f);
                        float h1 = fmaxf(p0[j][e] + p2[j][e] + bb, 0.0f);
                        hv[p] = fmaf(att[j][e], h0 - h1, h1);
                    }
                    int row = wm * 16 + g + eh * 8;
                    char* d = smem + SM_A + (colg >> 7) * TILE + swz(row, colg & 127);
                    *(__half2*)d = __floats2half2_rn(hv[0], hv[1]);
                }
            }
        }
    }

    // =====================================================================
    // L3 + L4: stages 8..17 (nh = u/5, kc = u%5); warp tile 32r x 32ch
    // =====================================================================
    float oat[2][4] = {};
    float xacc[2][4][4];
    const uint32_t aL3 = sb + SM_A + (uint32_t)((wm2 * 32 + aRow) * 256);
    const uint32_t bL3 = sb + SM_W + (uint32_t)((wn4 * 32 + bRow) * 256);

    for (int u = 0; u < 10; u++) {
        __syncthreads();   // prior stage reads done (u=0: h_i writes visible)
        prefetch32k(sb + SM_W, (const char*)g_wstage + (size_t)(8 + u) * WBLOB, t);
        CP_WAIT_ALL();
        __syncthreads();
        const int nh = u / 5, kc = u % 5;

        if (kc == 0) {
            #pragma unroll
            for (int i = 0; i < 2; i++)
                #pragma unroll
                for (int j = 0; j < 4; j++)
                    #pragma unroll
                    for (int e = 0; e < 4; e++) xacc[i][j][e] = 0.0f;
        }

        wgemm_l3(xacc, aL3 + (uint32_t)(kc * TILE), ax, aHi, bL3, bx, bHi);

        if (kc == 4) {
            float b3v[4][2];
            #pragma unroll
            for (int j = 0; j < 4; j++) {
                int c = nh * 128 + wn4 * 32 + j * 8 + 2 * tq;
                b3v[j][0] = __ldg(&b3[c]);
                b3v[j][1] = __ldg(&b3[c + 1]);
            }
            #pragma unroll
            for (int i = 0; i < 2; i++)
                #pragma unroll
                for (int kb4 = 0; kb4 < 2; kb4++) {
                    int j0 = kb4 * 2;
                    uint32_t af[4];
                    af[0] = packh2(fmaxf(xacc[i][j0][0]     + b3v[j0][0],     0.0f),
                                   fmaxf(xacc[i][j0][1]     + b3v[j0][1],     0.0f));
                    af[1] = packh2(fmaxf(xacc[i][j0][2]     + b3v[j0][0],     0.0f),
                                   fmaxf(xacc[i][j0][3]     + b3v[j0][1],     0.0f));
                    af[2] = packh2(fmaxf(xacc[i][j0 + 1][0] + b3v[j0 + 1][0], 0.0f),
                                   fmaxf(xacc[i][j0 + 1][1] + b3v[j0 + 1][1], 0.0f));
                    af[3] = packh2(fmaxf(xacc[i][j0 + 1][2] + b3v[j0 + 1][0], 0.0f),
                                   fmaxf(xacc[i][j0 + 1][3] + b3v[j0 + 1][1], 0.0f));
                    mma16816(oat[i], af, w4f[nh][kb4][0], w4f[nh][kb4][1]);
                }
        }
    }

    // ---- final: 4-way cross-wn4 reduction, bias, tanh, store ----
    __syncthreads();
    float* red = (float*)(smem + SM_W);   // 6KB, W buffer free now
    if (wn4 > 0) {
        #pragma unroll
        for (int i = 0; i < 2; i++) {
            int r0 = wm2 * 32 + i * 16 + g;
            *(float2*)&red[((wn4 - 1) * 64 + r0) * 8 + 2 * tq] =
                make_float2(oat[i][0], oat[i][1]);
            *(float2*)&red[((wn4 - 1) * 64 + r0 + 8) * 8 + 2 * tq] =
                make_float2(oat[i][2], oat[i][3]);
        }
    }
    __syncthreads();
    if (wn4 == 0) {
        float bb0 = __ldg(&b4[2 * tq]), bb1 = __ldg(&b4[2 * tq + 1]);
        #pragma unroll
        for (int i = 0; i < 2; i++) {
            int r0 = wm2 * 32 + i * 16 + g;
            size_t gr = (size_t)cta * 64 + r0;
            float s00 = oat[i][0], s01 = oat[i][1], s10 = oat[i][2], s11 = oat[i][3];
            #pragma unroll
            for (int w = 0; w < 3; w++) {
                float2 v0 = *(float2*)&red[(w * 64 + r0) * 8 + 2 * tq];
                float2 v1 = *(float2*)&red[(w * 64 + r0 + 8) * 8 + 2 * tq];
                s00 += v0.x; s01 += v0.y; s10 += v1.x; s11 += v1.y;
            }
            *(float2*)&out[gr * 8 + 2 * tq] =
                make_float2(tanhf(s00 + bb0), tanhf(s01 + bb1));
            *(float2*)&out[(gr + 8) * 8 + 2 * tq] =
                make_float2(tanhf(s10 + bb0), tanhf(s11 + bb1));
        }
    }
}

// ---------------------------------------------------------------------------
// kernel_launch — 2 launches, graph-capturable, allocation-free.
// Inputs: state, W1, b1, W2, b2, W3, b3, W4, b4
// ---------------------------------------------------------------------------
extern "C" void kernel_launch(void* const* d_in, const int* in_sizes, int n_in,
                              void* d_out, int out_size)
{
    const float* state = (const float*)d_in[0];
    const float* W1    = (const float*)d_in[1];
    const float* b1    = (const float*)d_in[2];
    const float* W2    = (const float*)d_in[3];
    const float* b2    = (const float*)d_in[4];
    const float* W3    = (const float*)d_in[5];
    const float* b3    = (const float*)d_in[6];
    const float* W4    = (const float*)d_in[7];
    const float* b4    = (const float*)d_in[8];
    float* out = (float*)d_out;

    cudaFuncSetAttribute(actor_main,
                         cudaFuncAttributeMaxDynamicSharedMemorySize, SMEM_BYTES);

    convert_weights<<<18, 256>>>(W1, W2, W3);
    actor_main<<<NCTA, 256, SMEM_BYTES>>>(state, b1, b2, b3, W4, b4, out);
}